// round 9
// baseline (speedup 1.0000x reference)
#include <cuda_runtime.h>
#include <math.h>

#define LTOT  13326
#define LPAD2 14464
#define NQ    4096
#define GUARD 4096
#define NG8   (LPAD2/8)
#define NSPLIT 8

__constant__ int   c_off [5] = {0, 4096, 7345, 9946, 11882};
__constant__ int   c_off2[5] = {0, 4368, 7856, 10672, 12800};
__constant__ int   c_ws  [5] = {64, 57, 51, 44, 38};
__constant__ float c_ratio[5]= {1.0f, 63.0f/56.0f, 63.0f/50.0f, 63.0f/43.0f, 63.0f/37.0f};

__device__ __align__(16) float g_mb  [2*32*NQ];
__device__ __align__(16) float g_m   [(size_t)2*32*LPAD2];
__device__ __align__(16) float g_base[(size_t)2*64*LPAD2];
__device__ __align__(16) float g_sq  [2*LPAD2];
__device__ __align__(16) float g_invb[(size_t)2*2*LPAD2];            // (10/nrm, bias)
__device__ __align__(16) float g_G   [(size_t)2*NQ*LPAD2 + 2*GUARD]; // G
__device__ __align__(16) float g_P   [(size_t)2*NQ*LPAD2 + 2*GUARD]; // scores, then E
__device__ __align__(16) float g_H   [(size_t)2*NQ*LPAD2 + 2*GUARD]; // W
__device__ __align__(16) float g_invs[2*NQ];
__device__ __align__(16) float g_part[(size_t)NSPLIT*2*64*NQ];

__device__ __forceinline__ float cubw(float d) {
    d = fabsf(d);
    if (d <= 1.0f) return ((1.25f*d - 2.25f)*d)*d + 1.0f;
    if (d <  2.0f) return ((-0.75f*d + 3.75f)*d - 6.0f)*d + 3.0f;
    return 0.0f;
}
__device__ __forceinline__ float fexp(float x) {
    float t = fmaxf(x * 1.4426950408889634f, -125.0f);
    int   ri = __float2int_rn(t);
    float f  = t - (float)ri;
    float z  = f * 0.6931471805599453f;
    float p  = 1.0f + z*(1.0f + z*(0.5f + z*(0.16666667f + z*(0.041666667f + z*0.0083333333f))));
    return __int_as_float((ri + 127) << 23) * p;
}
__device__ __forceinline__ void ldwin8(const float* p, float w[8]) {
    int d = (int)((((size_t)p) >> 2) & 3);
    const float4* ap = (const float4*)(p - d);
    float4 A = ap[0], B = ap[1], C = B;
    if (d) C = ap[2];
    if (d == 0)      { w[0]=A.x;w[1]=A.y;w[2]=A.z;w[3]=A.w;w[4]=B.x;w[5]=B.y;w[6]=B.z;w[7]=B.w; }
    else if (d == 1) { w[0]=A.y;w[1]=A.z;w[2]=A.w;w[3]=B.x;w[4]=B.y;w[5]=B.z;w[6]=B.w;w[7]=C.x; }
    else if (d == 2) { w[0]=A.z;w[1]=A.w;w[2]=B.x;w[3]=B.y;w[4]=B.z;w[5]=B.w;w[6]=C.x;w[7]=C.y; }
    else             { w[0]=A.w;w[1]=B.x;w[2]=B.y;w[3]=B.z;w[4]=B.w;w[5]=C.x;w[6]=C.y;w[7]=C.z; }
}
__device__ __forceinline__ int stride_of(int l) {
    if (l < 4368)  return 66;
    if (l < 7856)  return 59;
    if (l < 10672) return 53;
    if (l < 12800) return 46;
    return 40;
}

// ---------------- zero m/base ----------------
__global__ void k_zero() {
    size_t i = (size_t)blockIdx.x*blockDim.x + threadIdx.x;
    size_t nm = (size_t)2*32*LPAD2/4, nb = (size_t)2*64*LPAD2/4;
    float4 z = make_float4(0.f,0.f,0.f,0.f);
    for (; i < nm + nb; i += (size_t)gridDim.x*blockDim.x) {
        if (i < nm) ((float4*)g_m)[i] = z;
        else ((float4*)g_base)[i - nm] = z;
    }
}

// ---------------- match_base ----------------
__global__ void k_matchbase(const float* __restrict__ inp, const float* __restrict__ Wb,
                            const float* __restrict__ bb, const float* __restrict__ ap) {
    int idx = blockIdx.x * blockDim.x + threadIdx.x;
    if (idx >= 2*32*4096) return;
    int pos = idx & 4095, cm = (idx >> 12) & 31, b = idx >> 17;
    const float* x = inp + ((size_t)b*64)*4096 + pos;
    const float* w = Wb + cm*64;
    float acc = bb[cm];
#pragma unroll
    for (int c = 0; c < 64; c++) acc = fmaf(w[c], x[(size_t)c*4096], acc);
    float a = ap[0];
    g_mb[idx] = acc >= 0.0f ? acc : a*acc;
}

// ---------------- resize + conv (padded layout) ----------------
__global__ __launch_bounds__(128) void k_resize_conv(const float* __restrict__ ref,
        const float* __restrict__ Wm, const float* __restrict__ bmv,
        const float* __restrict__ Wa, const float* __restrict__ bav,
        const float* __restrict__ ap) {
    __shared__ float Wsh[96][65];
    __shared__ float bsh[96];
    __shared__ float rv[8][65];
    __shared__ int   l2sh[8];
    int b = blockIdx.y, t = threadIdx.x;
    for (int i = t; i < 96*64; i += 128) {
        int o = i >> 6, c = i & 63;
        Wsh[o][c] = (o < 32) ? Wm[o*64 + c] : Wa[(o-32)*64 + c];
    }
    if (t < 96) bsh[t] = (t < 32) ? bmv[t] : bav[t-32];
    float a = ap[0];
    int p0 = blockIdx.x * 8;
    if (t < 8) {
        int pos = p0 + t, v = -1;
        if (pos < LTOT) {
            int s = 0;
            while (s < 4 && pos >= c_off[s+1]) s++;
            int ws = c_ws[s], lp = pos - c_off[s];
            int y = lp / ws, x = lp - y*ws;
            v = c_off2[s] + (y+1)*(ws+2) + (x+1);
        }
        l2sh[t] = v;
    }
    for (int i = t; i < 512; i += 128) {
        int c = i >> 3, pi = i & 7;
        int pos = p0 + pi;
        float val = 0.0f;
        if (pos < LTOT) {
            int s = 0;
            while (s < 4 && pos >= c_off[s+1]) s++;
            int lp = pos - c_off[s];
            int ws = c_ws[s];
            int y = lp / ws, x = lp - y*ws;
            float ry = (float)y * c_ratio[s], rx = (float)x * c_ratio[s];
            int iy0 = (int)floorf(ry); float fy = ry - (float)iy0;
            int ix0 = (int)floorf(rx); float fx = rx - (float)ix0;
            float wyv[4] = {cubw(fy+1.0f), cubw(fy), cubw(1.0f-fy), cubw(2.0f-fy)};
            float wxv[4] = {cubw(fx+1.0f), cubw(fx), cubw(1.0f-fx), cubw(2.0f-fx)};
            const float* ch = ref + ((size_t)b*64 + c)*4096;
#pragma unroll
            for (int u = 0; u < 4; u++) {
                int yy = min(max(iy0 - 1 + u, 0), 63);
                const float* rowp = ch + yy*64;
                float racc = 0.0f;
#pragma unroll
                for (int v = 0; v < 4; v++)
                    racc = fmaf(wxv[v], rowp[min(max(ix0 - 1 + v, 0), 63)], racc);
                val = fmaf(wyv[u], racc, val);
            }
        }
        rv[pi][c] = val;
    }
    __syncthreads();
    for (int i = t; i < 768; i += 128) {
        int pi = i / 96, o = i % 96;
        int l2 = l2sh[pi];
        if (l2 < 0) continue;
        float acc = bsh[o];
#pragma unroll
        for (int c = 0; c < 64; c++) acc = fmaf(Wsh[o][c], rv[pi][c], acc);
        acc = acc >= 0.0f ? acc : a*acc;
        if (o < 32) g_m   [((size_t)b*32 + o)     *LPAD2 + l2] = acc;
        else        g_base[((size_t)b*64 + (o-32))*LPAD2 + l2] = acc;
    }
}

// ---------------- sq ----------------
__global__ void k_prep() {
    int l = blockIdx.x*128 + threadIdx.x;
    int b = blockIdx.y;
    if (l >= LPAD2) return;
    float a = 0.0f;
#pragma unroll
    for (int c = 0; c < 32; c++) {
        float v = g_m[((size_t)b*32 + c)*LPAD2 + l];
        a = fmaf(v, v, a);
    }
    g_sq[b*LPAD2 + l] = a;
}

// ---------------- invb ----------------
__global__ void k_invb() {
    int l = blockIdx.x*128 + threadIdx.x;
    int b = blockIdx.y;
    if (l >= LPAD2) return;
    int wd = 0, loc = 0;
    if      (l < 4356)                { wd=66; loc=l; }
    else if (l >= 4368  && l < 7849)  { wd=59; loc=l-4368; }
    else if (l >= 7856  && l < 10665) { wd=53; loc=l-7856; }
    else if (l >= 10672 && l < 12788) { wd=46; loc=l-10672; }
    else if (l >= 12800 && l < 14400) { wd=40; loc=l-12800; }
    float2 o = make_float2(0.0f, -1e30f);
    if (wd) {
        int y = loc / wd, x = loc - y*wd;
        if (y >= 1 && y <= wd-2 && x >= 1 && x <= wd-2) {
            float a = 0.0f;
#pragma unroll
            for (int dy = -1; dy <= 1; dy++)
#pragma unroll
                for (int dx = -1; dx <= 1; dx++)
                    a += g_sq[b*LPAD2 + l + dy*wd + dx];
            o = make_float2(10.0f / fmaxf(sqrtf(a), 1e-4f), 0.0f);
        }
    }
    ((float2*)g_invb)[(size_t)b*LPAD2 + l] = o;
}

// ---------------- G = mb^T * m ----------------
__global__ __launch_bounds__(256) void k_gemm_G() {
    const int b  = blockIdx.z;
    const int bm = blockIdx.y << 7, bn = blockIdx.x << 7;
    const float* A  = g_mb + (size_t)b*32*NQ;
    const float* Bm = g_m  + (size_t)b*32*LPAD2;
    float* G = g_G + GUARD + (size_t)b*NQ*LPAD2;
    __shared__ float As[32][128];
    __shared__ float Bs[32][128];
    const int t = threadIdx.x;
#pragma unroll
    for (int j = 0; j < 4; j++) {
        int id = t + j*256;
        int row = id >> 5, c4 = (id & 31) << 2;
        *(float4*)&As[row][c4] = *(const float4*)(A  + (size_t)row*NQ    + bm + c4);
        *(float4*)&Bs[row][c4] = *(const float4*)(Bm + (size_t)row*LPAD2 + bn + c4);
    }
    __syncthreads();
    const int ty = t >> 4, tx = t & 15;
    float acc[8][8] = {};
#pragma unroll
    for (int kk = 0; kk < 32; kk++) {
        float4 a0 = *(const float4*)&As[kk][ty << 3];
        float4 a1 = *(const float4*)&As[kk][(ty << 3) + 4];
        float4 b0 = *(const float4*)&Bs[kk][tx << 3];
        float4 b1 = *(const float4*)&Bs[kk][(tx << 3) + 4];
        float ra[8] = {a0.x,a0.y,a0.z,a0.w,a1.x,a1.y,a1.z,a1.w};
        float rb[8] = {b0.x,b0.y,b0.z,b0.w,b1.x,b1.y,b1.z,b1.w};
#pragma unroll
        for (int i = 0; i < 8; i++)
#pragma unroll
            for (int j = 0; j < 8; j++)
                acc[i][j] = fmaf(ra[i], rb[j], acc[i][j]);
    }
#pragma unroll
    for (int i = 0; i < 8; i++) {
        float* row = G + (size_t)(bm + (ty << 3) + i)*LPAD2 + bn + (tx << 3);
        *(float4*)row     = make_float4(acc[i][0],acc[i][1],acc[i][2],acc[i][3]);
        *(float4*)(row+4) = make_float4(acc[i][4],acc[i][5],acc[i][6],acc[i][7]);
    }
}

// ---------------- fused 9-tap score + softmax: G -> E (+invs) ----------------
__global__ __launch_bounds__(256) void k_scoreV() {
    int q = blockIdx.x, b = blockIdx.y;
    const float* Gb = g_G + GUARD + (size_t)b*NQ*LPAD2;
    float* D = g_P + GUARD + ((size_t)b*NQ + q)*LPAD2;
    const float2* ivb = ((const float2*)g_invb) + (size_t)b*LPAD2;
    int y = q >> 6, x = q & 63, t = threadIdx.x;
    const float* rp[9]; bool vv[9];
#pragma unroll
    for (int i = 0; i < 9; i++) {
        int dy = i/3 - 1, dx = i%3 - 1;
        vv[i] = ((unsigned)(y+dy) < 64u) && ((unsigned)(x+dx) < 64u);
        rp[i] = Gb + (size_t)(q + dy*64 + dx)*LPAD2;
    }
    float mx = -3e38f;
    for (int g = t; g < NG8; g += 256) {
        int l8 = g << 3;
        int st = stride_of(l8);
        float acc[8], w[8];
        float4 m0 = *(const float4*)(rp[4] + l8), m1 = *(const float4*)(rp[4] + l8 + 4);
        acc[0]=m0.x; acc[1]=m0.y; acc[2]=m0.z; acc[3]=m0.w;
        acc[4]=m1.x; acc[5]=m1.y; acc[6]=m1.z; acc[7]=m1.w;
#pragma unroll
        for (int i = 0; i < 9; i++) {
            if (i == 4) continue;
            if (!vv[i]) continue;
            int dy = i/3 - 1, dx = i%3 - 1;
            ldwin8(rp[i] + l8 + dy*st + dx, w);
#pragma unroll
            for (int e = 0; e < 8; e++) acc[e] += w[e];
        }
        float s[8];
#pragma unroll
        for (int k = 0; k < 4; k++) {
            float4 iv = *(const float4*)(ivb + l8 + 2*k);
            s[2*k]   = fmaf(acc[2*k],   iv.x, iv.y);
            s[2*k+1] = fmaf(acc[2*k+1], iv.z, iv.w);
            mx = fmaxf(mx, fmaxf(s[2*k], s[2*k+1]));
        }
        *(float4*)(D + l8)     = make_float4(s[0],s[1],s[2],s[3]);
        *(float4*)(D + l8 + 4) = make_float4(s[4],s[5],s[6],s[7]);
    }
    __shared__ float red[8];
    __shared__ float bc;
#pragma unroll
    for (int o = 16; o > 0; o >>= 1) mx = fmaxf(mx, __shfl_xor_sync(0xffffffffu, mx, o));
    if ((t & 31) == 0) red[t >> 5] = mx;
    __syncthreads();
    if (t == 0) {
        float m = red[0];
#pragma unroll
        for (int i = 1; i < 8; i++) m = fmaxf(m, red[i]);
        bc = m;
    }
    __syncthreads();
    float M = bc, sum = 0.0f;
    for (int g = t; g < NG8; g += 256) {
        int l8 = g << 3;
        float4 v0 = *(float4*)(D + l8), v1 = *(float4*)(D + l8 + 4);
        v0.x = fexp(v0.x - M); v0.y = fexp(v0.y - M);
        v0.z = fexp(v0.z - M); v0.w = fexp(v0.w - M);
        v1.x = fexp(v1.x - M); v1.y = fexp(v1.y - M);
        v1.z = fexp(v1.z - M); v1.w = fexp(v1.w - M);
        *(float4*)(D + l8)     = v0;
        *(float4*)(D + l8 + 4) = v1;
        sum += (v0.x + v0.y) + (v0.z + v0.w) + (v1.x + v1.y) + (v1.z + v1.w);
    }
#pragma unroll
    for (int o = 16; o > 0; o >>= 1) sum += __shfl_xor_sync(0xffffffffu, sum, o);
    if ((t & 31) == 0) red[t >> 5] = sum;
    __syncthreads();
    if (t == 0) {
        float s = 0.0f;
#pragma unroll
        for (int i = 0; i < 8; i++) s += red[i];
        g_invs[b*NQ + q] = 1.0f / s;
    }
}

// ---------------- fused 9-tap W: E -> W (per-tap invs scaling) ----------------
__global__ __launch_bounds__(256) void k_WV() {
    int q = blockIdx.x, b = blockIdx.y;
    const float* Eb = g_P + GUARD + (size_t)b*NQ*LPAD2;
    float* D = g_H + GUARD + ((size_t)b*NQ + q)*LPAD2;
    int y = q >> 6, x = q & 63, t = threadIdx.x;
    const float* rp[9]; float sc[9];
#pragma unroll
    for (int i = 0; i < 9; i++) {
        int dy = i/3 - 1, dx = i%3 - 1;
        int qq = q + dy*64 + dx;
        bool v = ((unsigned)(y+dy) < 64u) && ((unsigned)(x+dx) < 64u);
        sc[i] = v ? g_invs[b*NQ + qq] : 0.0f;
        rp[i] = Eb + (size_t)qq*LPAD2;
    }
    for (int g = t; g < NG8; g += 256) {
        int l8 = g << 3;
        int st = stride_of(l8);
        float acc[8], w[8];
        float4 m0 = *(const float4*)(rp[4] + l8), m1 = *(const float4*)(rp[4] + l8 + 4);
        float c4 = sc[4];
        acc[0]=c4*m0.x; acc[1]=c4*m0.y; acc[2]=c4*m0.z; acc[3]=c4*m0.w;
        acc[4]=c4*m1.x; acc[5]=c4*m1.y; acc[6]=c4*m1.z; acc[7]=c4*m1.w;
#pragma unroll
        for (int i = 0; i < 9; i++) {
            if (i == 4) continue;
            if (sc[i] == 0.0f) continue;
            int dy = i/3 - 1, dx = i%3 - 1;
            ldwin8(rp[i] + l8 + dy*st + dx, w);
#pragma unroll
            for (int e = 0; e < 8; e++) acc[e] = fmaf(sc[i], w[e], acc[e]);
        }
        *(float4*)(D + l8)     = make_float4(acc[0],acc[1],acc[2],acc[3]);
        *(float4*)(D + l8 + 4) = make_float4(acc[4],acc[5],acc[6],acc[7]);
    }
}

// ---------------- out_part = W * base^T (split-K=8) ----------------
__global__ __launch_bounds__(256) void k_gemm_W() {
    const int split = blockIdx.x;
    const int bm = blockIdx.y << 7;
    const int b  = blockIdx.z;
    const float* W  = g_H + GUARD + (size_t)b*NQ*LPAD2;
    const float* Bb = g_base + (size_t)b*64*LPAD2;
    __shared__ float As[8][128];
    __shared__ float Bs[8][64];
    const int t = threadIdx.x;
    const int ty = t >> 4, tx = t & 15;
    float acc[8][4] = {};
    const int kbeg = split * (LPAD2/8);
    const int arow = t >> 1, akc = (t & 1) << 2;
    const float* Aptr = W + (size_t)(bm + arow)*LPAD2 + akc;
    const int brow = (t & 127) >> 1;
    const float* Bptr = Bb + (size_t)brow*LPAD2 + akc;
    for (int k0 = kbeg; k0 < kbeg + LPAD2/8; k0 += 8) {
        float4 a4 = *(const float4*)(Aptr + k0);
        As[akc+0][arow] = a4.x; As[akc+1][arow] = a4.y;
        As[akc+2][arow] = a4.z; As[akc+3][arow] = a4.w;
        if (t < 128) {
            float4 b4 = *(const float4*)(Bptr + k0);
            Bs[akc+0][brow] = b4.x; Bs[akc+1][brow] = b4.y;
            Bs[akc+2][brow] = b4.z; Bs[akc+3][brow] = b4.w;
        }
        __syncthreads();
#pragma unroll
        for (int kk = 0; kk < 8; kk++) {
            float4 a0 = *(const float4*)&As[kk][ty << 3];
            float4 a1 = *(const float4*)&As[kk][(ty << 3) + 4];
            float4 b0 = *(const float4*)&Bs[kk][tx << 2];
            float ra[8] = {a0.x,a0.y,a0.z,a0.w,a1.x,a1.y,a1.z,a1.w};
            float rb[4] = {b0.x,b0.y,b0.z,b0.w};
#pragma unroll
            for (int i = 0; i < 8; i++)
#pragma unroll
                for (int j = 0; j < 4; j++)
                    acc[i][j] = fmaf(ra[i], rb[j], acc[i][j]);
        }
        __syncthreads();
    }
    float* pb = g_part + (size_t)(split*2 + b)*64*NQ;
#pragma unroll
    for (int j = 0; j < 4; j++) {
        int c = (tx << 2) + j;
        *(float4*)(pb + (size_t)c*NQ + bm + (ty << 3))     = make_float4(acc[0][j],acc[1][j],acc[2][j],acc[3][j]);
        *(float4*)(pb + (size_t)c*NQ + bm + (ty << 3) + 4) = make_float4(acc[4][j],acc[5][j],acc[6][j],acc[7][j]);
    }
}

// ---------------- reduce + residual ----------------
__global__ void k_final(const float* __restrict__ inp, float* __restrict__ out) {
    int idx = blockIdx.x * blockDim.x + threadIdx.x;
    if (idx >= 2*64*4096) return;
    int q = idx & 4095, c = (idx >> 12) & 63, b = idx >> 18;
    float s = 0.0f;
#pragma unroll
    for (int sp = 0; sp < NSPLIT; sp++)
        s += g_part[(size_t)(sp*2 + b)*64*NQ + (size_t)c*NQ + q];
    out[idx] = inp[idx] + 0.25f * s;
}

extern "C" void kernel_launch(void* const* d_in, const int* in_sizes, int n_in,
                              void* d_out, int out_size) {
    const float* input     = (const float*)d_in[0];
    const float* input_ref = (const float*)d_in[1];
    const float* Wb  = (const float*)d_in[2];
    const float* bbv = (const float*)d_in[3];
    const float* Wm  = (const float*)d_in[4];
    const float* bmv = (const float*)d_in[5];
    const float* Wa  = (const float*)d_in[6];
    const float* bav = (const float*)d_in[7];
    const float* ap  = (const float*)d_in[8];
    float* out = (float*)d_out;

    k_zero       <<<1024, 256>>>();
    k_matchbase  <<<1024, 256>>>(input, Wb, bbv, ap);
    k_resize_conv<<<dim3(1666, 2), 128>>>(input_ref, Wm, bmv, Wa, bav, ap);
    k_prep       <<<dim3(113, 2), 128>>>();
    k_invb       <<<dim3(113, 2), 128>>>();
    k_gemm_G     <<<dim3(113, 32, 2), 256>>>();
    k_scoreV     <<<dim3(NQ, 2), 256>>>();           // 9-tap from G -> E + invs
    k_WV         <<<dim3(NQ, 2), 256>>>();           // 9-tap from E -> W
    k_gemm_W     <<<dim3(NSPLIT, 32, 2), 256>>>();
    k_final      <<<2048, 256>>>(input, out);
}